// round 12
// baseline (speedup 1.0000x reference)
#include <cuda_runtime.h>
#include <cstddef>

#define BATCH 512
#define TT    512
#define DD    128
#define DOUTN 32
#define CCLS  4
#define TBK   32            // timesteps per tile
#define NTILE (TT / TBK)    // 16
#define RP    33            // r/x tile pitch (bank-conflict-free)

#define ALPHA_C 0.1f
#define GAMMA_C 0.9f
#define EPS_C   1e-5f
#define EPSH_C  1e-6f
#define LNEPS_C 1e-5f

__device__ __forceinline__ float warp_sum(float v) {
#pragma unroll
    for (int s = 16; s > 0; s >>= 1)
        v += __shfl_xor_sync(0xffffffffu, v, s, 32);
    return v;
}

__device__ __forceinline__ unsigned long long fma2(unsigned long long a,
                                                   unsigned long long b,
                                                   unsigned long long c) {
    unsigned long long d;
    asm("fma.rn.f32x2 %0, %1, %2, %3;" : "=l"(d) : "l"(a), "l"(b), "l"(c));
    return d;
}

__device__ __forceinline__ unsigned long long add2(unsigned long long a,
                                                   unsigned long long b) {
    unsigned long long d;
    asm("add.rn.f32x2 %0, %1, %2;" : "=l"(d) : "l"(a), "l"(b));
    return d;
}

__device__ __forceinline__ unsigned long long pack2(float lo, float hi) {
    unsigned long long r;
    asm("mov.b64 %0, {%1, %2};" : "=l"(r) : "f"(lo), "f"(hi));
    return r;
}

__device__ __forceinline__ void unpack2(unsigned long long v, float& lo, float& hi) {
    asm("mov.b64 {%0, %1}, %2;" : "=f"(lo), "=f"(hi) : "l"(v));
}

__global__ __launch_bounds__(128, 2)
void sync_head_kernel(const float* __restrict__ z_ticks,
                      const float* __restrict__ proj,
                      const float* __restrict__ ln_w,
                      const float* __restrict__ ln_b,
                      const float* __restrict__ cls_w,
                      const float* __restrict__ cls_b,
                      float* __restrict__ out_x,
                      float* __restrict__ out_logits) {
    // smem: ~37.6 KB -> 2 CTAs/SM
    __shared__ __align__(16) float smz[TBK * DD];    // z -> (z - m) -> z_tilde
    __shared__ __align__(16) float smM2[TBK * DD];   // M2[t][d]
    __shared__ float smr[TBK * RP];                  // r -> x, padded
    __shared__ float4 pcs[TBK];                      // {itau, c1, c2c, inv_s}
    __shared__ float c2arg[TBK];                     // alpha*vbar-ish + EPS term
    __shared__ __align__(16) float A[DOUTN][CCLS];
    __shared__ float4 SaV, SbV;

    const int tid  = threadIdx.x;
    const int lane = tid & 31;
    const int w    = tid >> 5;
    const int b    = blockIdx.x;

    // ---- folded LN x classifier constants ----
    {
        int j = tid >> 2, c = tid & 3;               // exactly 128 entries
        A[j][c] = ln_w[j] * cls_w[c * DOUTN + j];
    }
    if (tid < 2 * CCLS) {
        int c = tid & 3;
        float acc = 0.f;
        if (tid < CCLS) {
            for (int j = 0; j < DOUTN; j++) acc += ln_w[j] * cls_w[c * DOUTN + j];
            ((float*)&SaV)[c] = acc;
        } else {
            for (int j = 0; j < DOUTN; j++) acc += ln_b[j] * cls_w[c * DOUTN + j];
            ((float*)&SbV)[c] = acc + cls_b[c];
        }
    }

    // ---- proj column `lane` in registers, packed for f32x2 FMA ----
    unsigned long long q[DD / 2];
#pragma unroll
    for (int i = 0; i < DD / 2; i++) {
        float a = proj[(2 * i) * DOUTN + lane];
        float bb = proj[(2 * i + 1) * DOUTN + lane];
        q[i] = pack2(a, bb);
    }
    __syncthreads();
    const float4 Sa4 = SaV;
    const float4 Sb4 = SbV;

    const float4* zg4 = (const float4*)(z_ticks + (size_t)b * TT * DD);
    float* oxb  = out_x + (size_t)b * TT * DOUTN;
    float4* olb = (float4*)(out_logits + (size_t)b * TT * CCLS);

    // persistent per-thread carries
    float S1c = 0.f, S2c = 0.f;   // thread = dim d (tid), prefix sums
    float hj  = 0.f;              // tid < 32: EMA state for feature j = tid

#pragma unroll 1
    for (int tile = 0; tile < NTILE; tile++) {
        const int tb = tile * TBK;

        // ---- phase 1: load z tile (coalesced) + per-t constants ----
        {
            const float4* src = zg4 + (size_t)tb * (DD / 4);
            float4* dst = (float4*)smz;
#pragma unroll
            for (int k = 0; k < 8; k++)
                dst[tid + 128 * k] = src[tid + 128 * k];
        }
        if (tid < TBK) {
            const float tau   = (float)(tb + tid + 1);
            const float itau  = 1.0f / tau;
            const float denom = fmaxf(tau - 1.0f, 1.0f);
            const float idn   = 1.0f / denom;
            const float g     = __powf(GAMMA_C, tau);
            pcs[tid] = make_float4(itau,
                                   (1.0f - ALPHA_C) * idn,
                                   ALPHA_C * idn * (1.0f / 128.0f),
                                   (1.0f - GAMMA_C) / (1.0f - g));
        }
        __syncthreads();

        // ---- phase 2: scan over t for dim d = tid ----
        {
            const int d = tid;
#pragma unroll
            for (int t = 0; t < TBK; t++) {
                const float zz = smz[t * DD + d];
                S1c += zz;
                S2c = fmaf(zz, zz, S2c);
                const float m   = S1c * pcs[t].x;
                const float num = zz - m;
                const float M2  = fmaf(-m, S1c, S2c);
                smz[t * DD + d]  = num;
                smM2[t * DD + d] = M2;
            }
        }
        __syncthreads();

        // ---- phase 3: vbar per t (warp w handles t = 8w .. 8w+7) ----
        {
#pragma unroll
            for (int k = 0; k < 8; k++) {
                const int t = w * 8 + k;
                const float* row = smM2 + t * DD;
                float v = (row[lane] + row[lane + 32]) +
                          (row[lane + 64] + row[lane + 96]);
                v = warp_sum(v);
                if (lane == 0)
                    c2arg[t] = fmaf(v, pcs[t].z, EPS_C);
            }
        }
        __syncthreads();

        // ---- phase 4: z_tilde pointwise (32 elems per thread) ----
        {
            const int t  = tid >> 2;
            const int f4 = (tid & 3) * 8;              // float4 index base in row
            const float c1t = pcs[t].y;
            const float vb  = c2arg[t];
            float4* zrow  = (float4*)(smz + t * DD);
            float4* m2row = (float4*)(smM2 + t * DD);
#pragma unroll
            for (int k = 0; k < 8; k++) {
                float4 nm = zrow[f4 + k];
                float4 m2 = m2row[f4 + k];
                float4 zt;
                zt.x = nm.x * rsqrtf(fmaf(m2.x, c1t, vb));
                zt.y = nm.y * rsqrtf(fmaf(m2.y, c1t, vb));
                zt.z = nm.z * rsqrtf(fmaf(m2.z, c1t, vb));
                zt.w = nm.w * rsqrtf(fmaf(m2.w, c1t, vb));
                zrow[f4 + k] = zt;
            }
        }
        __syncthreads();

        // ---- phase 5: matvec per t (warp w: t = 8w..8w+7), q in regs ----
        {
#pragma unroll
            for (int k = 0; k < 8; k++) {
                const int t = w * 8 + k;
                const ulonglong2* zp = (const ulonglong2*)(smz + t * DD);
                unsigned long long acc0 = 0ull, acc1 = 0ull, acc2 = 0ull, acc3 = 0ull;
#pragma unroll
                for (int c = 0; c < 16; c++) {
                    ulonglong2 za = zp[2 * c];
                    ulonglong2 zc = zp[2 * c + 1];
                    acc0 = fma2(za.x, q[4 * c + 0], acc0);
                    acc1 = fma2(za.y, q[4 * c + 1], acc1);
                    acc2 = fma2(zc.x, q[4 * c + 2], acc2);
                    acc3 = fma2(zc.y, q[4 * c + 3], acc3);
                }
                unsigned long long sT = add2(add2(acc0, acc1), add2(acc2, acc3));
                float rlo, rhi;
                unpack2(sT, rlo, rhi);
                smr[t * RP + lane] = rlo + rhi;
            }
        }
        __syncthreads();

        // ---- phase 6: h EMA scan + log feature (threads 0..31, j = tid) ----
        if (tid < DOUTN) {
            const int j = tid;
#pragma unroll
            for (int t = 0; t < TBK; t++) {
                const float r = smr[t * RP + j];
                hj = fmaf(r, r, GAMMA_C * hj);
                smr[t * RP + j] = __logf(fmaf(hj, pcs[t].w, EPSH_C));
            }
        }
        __syncthreads();

        // ---- phase 7: copy x to global (all threads) + LN/logits (t=tid<32) ----
        {
            float* oxt = oxb + (size_t)tb * DOUTN;
#pragma unroll
            for (int k = 0; k < 8; k++) {
                const int i = tid + 128 * k;           // 0..1023
                const int t = i >> 5, j = i & 31;
                oxt[i] = smr[t * RP + j];
            }
        }
        if (tid < TBK) {
            const int t = tid;
            float sx = 0.f, sx2 = 0.f;
            float dt0 = 0.f, dt1 = 0.f, dt2 = 0.f, dt3 = 0.f;
#pragma unroll
            for (int j = 0; j < DOUTN; j++) {
                const float xj = smr[t * RP + j];
                const float4 Aj = *(const float4*)&A[j][0];
                sx  += xj;
                sx2 = fmaf(xj, xj, sx2);
                dt0 = fmaf(xj, Aj.x, dt0);
                dt1 = fmaf(xj, Aj.y, dt1);
                dt2 = fmaf(xj, Aj.z, dt2);
                dt3 = fmaf(xj, Aj.w, dt3);
            }
            const float mu      = sx * (1.0f / 32.0f);
            const float var     = fmaxf(fmaf(sx2, 1.0f / 32.0f, -mu * mu), 0.0f);
            const float inv_std = rsqrtf(var + LNEPS_C);
            float4 lg;
            lg.x = fmaf(inv_std, fmaf(-mu, Sa4.x, dt0), Sb4.x);
            lg.y = fmaf(inv_std, fmaf(-mu, Sa4.y, dt1), Sb4.y);
            lg.z = fmaf(inv_std, fmaf(-mu, Sa4.z, dt2), Sb4.z);
            lg.w = fmaf(inv_std, fmaf(-mu, Sa4.w, dt3), Sb4.w);
            olb[tb + t] = lg;
        }
        __syncthreads();   // protect smz/smM2/smr before next tile
    }
}

extern "C" void kernel_launch(void* const* d_in, const int* in_sizes, int n_in,
                              void* d_out, int out_size) {
    const float* z_ticks = (const float*)d_in[0];
    const float* proj    = (const float*)d_in[1];
    const float* ln_w    = (const float*)d_in[2];
    const float* ln_b    = (const float*)d_in[3];
    const float* cls_w   = (const float*)d_in[4];
    const float* cls_b   = (const float*)d_in[5];

    float* out_x      = (float*)d_out;
    float* out_logits = out_x + (size_t)BATCH * TT * DOUTN;

    sync_head_kernel<<<BATCH, 128>>>(z_ticks, proj, ln_w, ln_b,
                                     cls_w, cls_b, out_x, out_logits);
}

// round 13
// speedup vs baseline: 1.8507x; 1.8507x over previous
#include <cuda_runtime.h>
#include <cstddef>
#include <cstdint>

#define BATCH 512
#define TT    512
#define DD    128
#define DOUTN 32
#define CCLS  4
#define TBK   32
#define NTILE (TT / TBK)
#define RP    33
#define PLP   25            // partial-sum pitch (floats), conflict-free

#define ALPHA_C 0.1f
#define GAMMA_C 0.9f
#define EPS_C   1e-5f
#define EPSH_C  1e-6f
#define LNEPS_C 1e-5f

__device__ __forceinline__ float warp_sum(float v) {
#pragma unroll
    for (int s = 16; s > 0; s >>= 1)
        v += __shfl_xor_sync(0xffffffffu, v, s, 32);
    return v;
}

__device__ __forceinline__ unsigned long long fma2(unsigned long long a,
                                                   unsigned long long b,
                                                   unsigned long long c) {
    unsigned long long d;
    asm("fma.rn.f32x2 %0, %1, %2, %3;" : "=l"(d) : "l"(a), "l"(b), "l"(c));
    return d;
}

__device__ __forceinline__ unsigned long long add2(unsigned long long a,
                                                   unsigned long long b) {
    unsigned long long d;
    asm("add.rn.f32x2 %0, %1, %2;" : "=l"(d) : "l"(a), "l"(b));
    return d;
}

__device__ __forceinline__ unsigned long long pack2(float lo, float hi) {
    unsigned long long r;
    asm("mov.b64 %0, {%1, %2};" : "=l"(r) : "f"(lo), "f"(hi));
    return r;
}

__device__ __forceinline__ void unpack2(unsigned long long v, float& lo, float& hi) {
    asm("mov.b64 {%0, %1}, %2;" : "=f"(lo), "=f"(hi) : "l"(v));
}

__device__ __forceinline__ uint32_t sm_u32(const void* p) {
    uint32_t a;
    asm("{ .reg .u64 t; cvta.to.shared.u64 t, %1; cvt.u32.u64 %0, t; }"
        : "=r"(a) : "l"(p));
    return a;
}

__device__ __forceinline__ void cpa16(uint32_t dst, const void* src) {
    asm volatile("cp.async.cg.shared.global [%0], [%1], 16;" :: "r"(dst), "l"(src));
}
__device__ __forceinline__ void cpa_commit() {
    asm volatile("cp.async.commit_group;");
}
__device__ __forceinline__ void cpa_wait1() {
    asm volatile("cp.async.wait_group 1;");
}
__device__ __forceinline__ void cpa_wait0() {
    asm volatile("cp.async.wait_group 0;");
}

__global__ __launch_bounds__(128, 2)
void sync_head_kernel(const float* __restrict__ z_ticks,
                      const float* __restrict__ proj,
                      const float* __restrict__ ln_w,
                      const float* __restrict__ ln_b,
                      const float* __restrict__ cls_w,
                      const float* __restrict__ cls_b,
                      float* __restrict__ out_x,
                      float* __restrict__ out_logits) {
    __shared__ __align__(16) float smz[2][TBK * DD];   // z -> num -> z_tilde (dbl buf)
    __shared__ __align__(16) float smM2[TBK * DD];
    __shared__ float smr[TBK * RP];                    // r -> x
    __shared__ float pci[TBK], pcy[TBK], pcz[TBK], pcw[TBK];
    __shared__ float pl[TBK * PLP];                    // LN partials
    __shared__ __align__(16) float A[DOUTN][CCLS];
    __shared__ float4 SaV, SbV;

    const int tid  = threadIdx.x;
    const int lane = tid & 31;
    const int w    = tid >> 5;
    const int b    = blockIdx.x;

    // ---- folded LN x classifier constants ----
    {
        int j = tid >> 2, c = tid & 3;
        A[j][c] = ln_w[j] * cls_w[c * DOUTN + j];
    }
    if (tid < 2 * CCLS) {
        int c = tid & 3;
        float acc = 0.f;
        if (tid < CCLS) {
            for (int j = 0; j < DOUTN; j++) acc += ln_w[j] * cls_w[c * DOUTN + j];
            ((float*)&SaV)[c] = acc;
        } else {
            for (int j = 0; j < DOUTN; j++) acc += ln_b[j] * cls_w[c * DOUTN + j];
            ((float*)&SbV)[c] = acc + cls_b[c];
        }
    }

    // ---- proj column `lane` in registers ----
    unsigned long long q[DD / 2];
#pragma unroll
    for (int i = 0; i < DD / 2; i++) {
        float a  = proj[(2 * i) * DOUTN + lane];
        float bb = proj[(2 * i + 1) * DOUTN + lane];
        q[i] = pack2(a, bb);
    }

    const float4* zg4 = (const float4*)(z_ticks + (size_t)b * TT * DD);
    float* oxb  = out_x + (size_t)b * TT * DOUTN;
    float4* olb = (float4*)(out_logits + (size_t)b * TT * CCLS);

    // per-lane gamma powers for the h prefix-scan (lane = t within tile)
    const float gmn = __powf(GAMMA_C, -(float)lane);   // gamma^{-t}
    const float gpp = __powf(GAMMA_C,  (float)lane);   // gamma^{ t}

    // ---- prefetch tile 0 ----
    {
        const uint32_t dst0 = sm_u32(&smz[0][0]);
        const float4* src = zg4;
#pragma unroll
        for (int k = 0; k < 8; k++)
            cpa16(dst0 + (tid + 128 * k) * 16, src + tid + 128 * k);
        cpa_commit();
    }
    __syncthreads();
    const float4 Sa4 = SaV;
    const float4 Sb4 = SbV;

    // persistent carries
    float S1c = 0.f, S2c = 0.f;     // prefix sums for dim d = tid
    float hc[8];                    // h carry for this warp's 8 features
#pragma unroll
    for (int i = 0; i < 8; i++) hc[i] = 0.f;

#pragma unroll 1
    for (int tile = 0; tile < NTILE; tile++) {
        const int tb  = tile * TBK;
        const int cur = tile & 1;
        const int nxt = cur ^ 1;

        // per-tile constants (warp 0) — other warps may still be in prev 7b,
        // which touches only smr/pl, so no race on pc*.
        if (tid < TBK) {
            const float tau   = (float)(tb + tid + 1);
            const float denom = fmaxf(tau - 1.0f, 1.0f);
            const float idn   = 1.0f / denom;
            pci[tid] = 1.0f / tau;
            pcy[tid] = (1.0f - ALPHA_C) * idn;
            pcz[tid] = ALPHA_C * idn * (1.0f / 128.0f);
            pcw[tid] = (1.0f - GAMMA_C) / (1.0f - __powf(GAMMA_C, tau));
        }

        // prefetch next tile into the other buffer
        if (tile + 1 < NTILE) {
            const uint32_t dstn = sm_u32(&smz[nxt][0]);
            const float4* src = zg4 + (size_t)(tb + TBK) * (DD / 4);
#pragma unroll
            for (int k = 0; k < 8; k++)
                cpa16(dstn + (tid + 128 * k) * 16, src + tid + 128 * k);
            cpa_commit();
            cpa_wait1();      // current tile's group done
        } else {
            cpa_wait0();
        }
        __syncthreads();      // B1: z[cur] visible to all; pc* ready; smem reuse safe

        // ---- phase 2: prefix scan over t for dim d = tid ----
        {
            float* zc = smz[cur];
#pragma unroll
            for (int t = 0; t < TBK; t++) {
                const float zz = zc[t * DD + tid];
                S1c += zz;
                S2c = fmaf(zz, zz, S2c);
                const float m   = S1c * pci[t];
                zc[t * DD + tid]   = zz - m;              // num
                smM2[t * DD + tid] = fmaf(-m, S1c, S2c);  // M2
            }
        }
        __syncthreads();      // B2

        // ---- phases 3-5 (warp-local rows t = 8w..8w+7) ----
        {
            float c2v[8], c1v[8];
#pragma unroll
            for (int k = 0; k < 8; k++) {
                const int t = w * 8 + k;
                const float* row = smM2 + t * DD;
                float v = (row[lane] + row[lane + 32]) +
                          (row[lane + 64] + row[lane + 96]);
                v = warp_sum(v);
                c2v[k] = fmaf(v, pcz[t], EPS_C);
                c1v[k] = pcy[t];
            }
#pragma unroll
            for (int k = 0; k < 8; k++) {
                const int t = w * 8 + k;
                float4* zrow  = (float4*)(smz[cur] + t * DD);
                float4* m2row = (float4*)(smM2 + t * DD);
                float4 nm = zrow[lane];
                float4 m2 = m2row[lane];
                float4 zt;
                zt.x = nm.x * rsqrtf(fmaf(m2.x, c1v[k], c2v[k]));
                zt.y = nm.y * rsqrtf(fmaf(m2.y, c1v[k], c2v[k]));
                zt.z = nm.z * rsqrtf(fmaf(m2.z, c1v[k], c2v[k]));
                zt.w = nm.w * rsqrtf(fmaf(m2.w, c1v[k], c2v[k]));
                zrow[lane] = zt;
            }
            __syncwarp();
#pragma unroll
            for (int k = 0; k < 8; k++) {
                const int t = w * 8 + k;
                const ulonglong2* zp = (const ulonglong2*)(smz[cur] + t * DD);
                unsigned long long a0 = 0ull, a1 = 0ull, a2 = 0ull, a3 = 0ull;
#pragma unroll
                for (int c = 0; c < 16; c++) {
                    ulonglong2 za = zp[2 * c];
                    ulonglong2 zc = zp[2 * c + 1];
                    a0 = fma2(za.x, q[4 * c + 0], a0);
                    a1 = fma2(za.y, q[4 * c + 1], a1);
                    a2 = fma2(zc.x, q[4 * c + 2], a2);
                    a3 = fma2(zc.y, q[4 * c + 3], a3);
                }
                unsigned long long sT = add2(add2(a0, a1), add2(a2, a3));
                float rlo, rhi;
                unpack2(sT, rlo, rhi);
                smr[t * RP + lane] = rlo + rhi;
            }
        }
        __syncthreads();      // B3: all r ready

        // ---- phase 6+7a: parallel h-scan (lane = t) + LN partials ----
        {
            const float invs = pcw[lane];
            float sx = 0.f, sx2 = 0.f;
            float d0 = 0.f, d1 = 0.f, d2 = 0.f, d3 = 0.f;
#pragma unroll
            for (int i = 0; i < 8; i++) {
                const int j = w * 8 + i;
                const float r = smr[lane * RP + j];
                float pf = r * r * gmn;          // gamma^{-t} r^2
#pragma unroll
                for (int s = 1; s < 32; s <<= 1) {
                    float o = __shfl_up_sync(0xffffffffu, pf, s, 32);
                    if (lane >= s) pf += o;
                }
                const float h = gpp * fmaf(GAMMA_C, hc[i], pf);
                hc[i] = __shfl_sync(0xffffffffu, h, 31, 32);
                const float x = __logf(fmaf(h, invs, EPSH_C));
                smr[lane * RP + j] = x;
                const float4 Aj = *(const float4*)&A[j][0];
                sx  += x;
                sx2 = fmaf(x, x, sx2);
                d0 = fmaf(x, Aj.x, d0);
                d1 = fmaf(x, Aj.y, d1);
                d2 = fmaf(x, Aj.z, d2);
                d3 = fmaf(x, Aj.w, d3);
            }
            float* p = pl + lane * PLP + w * 6;
            p[0] = sx;  p[1] = sx2;
            p[2] = d0;  p[3] = d1;  p[4] = d2;  p[5] = d3;
        }
        __syncthreads();      // B4: x + partials ready

        // ---- phase 7b: x store (all threads) + LN finish (warp 0) ----
        {
#pragma unroll
            for (int it = 0; it < 2; it++) {
                const int g  = tid + 128 * it;       // quad index 0..255
                const int t  = g >> 3;
                const int j0 = (g & 7) * 4;
                float4 v;
                v.x = smr[t * RP + j0 + 0];
                v.y = smr[t * RP + j0 + 1];
                v.z = smr[t * RP + j0 + 2];
                v.w = smr[t * RP + j0 + 3];
                ((float4*)(oxb + (size_t)(tb + t) * DOUTN))[g & 7] = v;
            }
        }
        if (tid < TBK) {
            const int t = tid;
            float sx = 0.f, sx2 = 0.f, d0 = 0.f, d1 = 0.f, d2 = 0.f, d3 = 0.f;
#pragma unroll
            for (int w2 = 0; w2 < 4; w2++) {
                const float* p = pl + t * PLP + w2 * 6;
                sx  += p[0];  sx2 += p[1];
                d0  += p[2];  d1  += p[3];
                d2  += p[4];  d3  += p[5];
            }
            const float mu      = sx * (1.0f / 32.0f);
            const float var     = fmaxf(fmaf(sx2, 1.0f / 32.0f, -mu * mu), 0.0f);
            const float inv_std = rsqrtf(var + LNEPS_C);
            float4 lg;
            lg.x = fmaf(inv_std, fmaf(-mu, Sa4.x, d0), Sb4.x);
            lg.y = fmaf(inv_std, fmaf(-mu, Sa4.y, d1), Sb4.y);
            lg.z = fmaf(inv_std, fmaf(-mu, Sa4.z, d2), Sb4.z);
            lg.w = fmaf(inv_std, fmaf(-mu, Sa4.w, d3), Sb4.w);
            olb[tb + t] = lg;
        }
        // no end barrier: next tile's B1 orders smr/pl reuse
    }
}

extern "C" void kernel_launch(void* const* d_in, const int* in_sizes, int n_in,
                              void* d_out, int out_size) {
    const float* z_ticks = (const float*)d_in[0];
    const float* proj    = (const float*)d_in[1];
    const float* ln_w    = (const float*)d_in[2];
    const float* ln_b    = (const float*)d_in[3];
    const float* cls_w   = (const float*)d_in[4];
    const float* cls_b   = (const float*)d_in[5];

    float* out_x      = (float*)d_out;
    float* out_logits = out_x + (size_t)BATCH * TT * DOUTN;

    sync_head_kernel<<<BATCH, 128>>>(z_ticks, proj, ln_w, ln_b,
                                     cls_w, cls_b, out_x, out_logits);
}